// round 15
// baseline (speedup 1.0000x reference)
#include <cuda_runtime.h>
#include <cuda_fp16.h>
#include <math.h>

#define Bb 32
#define EPSV 0.05f
#define INV_EPS 20.0f
#define SHIFT 10.0f
#define NITERS 50
#define NTHR 512            // 16 warps; warp owns 8 rows

// ---------------------------------------------------------------------------
__device__ __forceinline__ unsigned smem_u32(const void* p) {
    unsigned a;
    asm("{ .reg .u64 t; cvta.to.shared.u64 t, %1; cvt.u32.u64 %0, t; }"
        : "=r"(a) : "l"(p));
    return a;
}
__device__ __forceinline__ unsigned mapa_rank(unsigned addr, int rank) {
    unsigned r;
    asm("mapa.shared::cluster.u32 %0, %1, %2;" : "=r"(r) : "r"(addr), "r"(rank));
    return r;
}
__device__ __forceinline__ void st_cluster_f32(unsigned addr, float v) {
    asm volatile("st.shared::cluster.f32 [%0], %1;" :: "r"(addr), "f"(v));
}
#define CLUSTER_SYNC() do { \
    asm volatile("barrier.cluster.arrive.aligned;" ::: "memory"); \
    asm volatile("barrier.cluster.wait.aligned;"   ::: "memory"); \
} while (0)

// Blackwell packed dual-FP32 math (PTX-only path)
#define FMA2(d, a, b, c) \
    asm("fma.rn.f32x2 %0, %1, %2, %3;" : "=l"(d) : "l"(a), "l"(b), "l"(c))
#define PACK2(d, x, y) \
    asm("mov.b64 %0, {%1, %2};" : "=l"(d) : "f"(x), "f"(y))
#define UNPACK2(x, y, d) \
    asm("mov.b64 {%0, %1}, %2;" : "=f"(x), "=f"(y) : "l"(d))

// ---------------------------------------------------------------------------
// ONE kernel. grid = 128, block = 512, cluster(4) = 1 batch.
// smem: ev[512] | cpart[16*512] | inbox[2][4][512] | row_mn[128] | ot_in[4]
//       | pad[4] | tile half[128*512]  (tile 16B-aligned)
__global__ void __launch_bounds__(NTHR, 1) __cluster_dims__(4, 1, 1)
emd_fused_kernel(const float* __restrict__ a_mask, const float* __restrict__ pc_a,
                 const float* __restrict__ b_mask, const float* __restrict__ pc_b,
                 float* __restrict__ out)
{
    extern __shared__ float smem[];
    float*  ev     = smem;                       // 512
    float*  cpart  = smem + 512;                 // 8192
    float*  inbox  = smem + 512 + 8192;          // 4096 (2 buf x 4 slot x 512)
    float*  row_mn = smem + 512 + 8192 + 4096;   // 128
    float*  ot_in  = row_mn + 128;               // 4 (+4 pad)
    __half* tile   = (__half*)(smem + 512 + 8192 + 4096 + 128 + 8); // 16B-aligned

    const int batch = blockIdx.x >> 2, slot = blockIdx.x & 3;
    const int row_base = slot * 128;
    const int t = threadIdx.x, w = t >> 5, lane = t & 31;

    // ---------------- prep (each CTA computes full-batch stats) -------------
    int gb = batch * 512 + t;
    float apt = a_mask[gb] * pc_a[gb * 3 + 2];
    float bpt = b_mask[gb] * pc_b[gb * 3 + 2];
    inbox[t] = apt;                              // stash (buffer0, dead by it1)
    cpart[t] = apt; cpart[512 + t] = bpt; cpart[1024 + t] = (bpt > 0.f) ? 0.f : 1.f;
    __syncthreads();
    for (int o = 256; o; o >>= 1) {
        if (t < o) {
            cpart[t]        += cpart[t + o];
            cpart[512 + t]  += cpart[512 + t + o];
            cpart[1024 + t] += cpart[1024 + t + o];
        }
        __syncthreads();
    }
    const float sa = cpart[0], sb = cpart[512], mmask = cpart[1024];
    const float bh = bpt / sb;                   // masked -> 0
    __syncthreads();

    // overlay b columns into cpart
    cpart[t]        = pc_b[gb * 3 + 0];
    cpart[512 + t]  = pc_b[gb * 3 + 1];
    cpart[1024 + t] = bpt;
    __syncthreads();
    const float* bxs = cpart;
    const float* bys = cpart + 512;
    const float* bvs = cpart + 1024;

    // ---------------- build SMEM tile ----------------
    // t_ij = exp((dmin_i - d_ij)*INV_EPS + SHIFT), 0 for masked pairs.
    float ahr[8], scr[8];
#pragma unroll
    for (int r = 0; r < 8; r++) {
        int row  = w * 8 + r;
        int grow = batch * 512 + row_base + row;
        float ax = pc_a[grow * 3 + 0], ay = pc_a[grow * 3 + 1];
        float ah = inbox[row_base + row] / sa;
        ahr[r] = ah;

        float dv[16], mn = 1e30f;
#pragma unroll
        for (int k = 0; k < 16; k++) {
            int j = k * 32 + lane;
            float dx = ax - bxs[j], dy = ay - bys[j];
            float d = sqrtf(__fmaf_rn(dx, dx, __fmaf_rn(dy, dy, 1e-12f)));
            dv[k] = d;
            if (bvs[j] > 0.f) mn = fminf(mn, d);
        }
#pragma unroll
        for (int o = 16; o; o >>= 1) mn = fminf(mn, __shfl_xor_sync(0xFFFFFFFFu, mn, o));
        if (lane == 0) row_mn[row] = mn;
        scr[r] = __expf(-__fmaf_rn(INV_EPS, mn, SHIFT));   // e^{-20*mn-SHIFT}

#pragma unroll
        for (int k = 0; k < 16; k++) {
            int j = k * 32 + lane;
            float arg = fminf((mn - dv[k]) * INV_EPS, 0.f) + SHIFT;
            float tv  = (bvs[j] > 0.f && ah > 0.f) ? __expf(arg) : 0.f;
            tile[row * 512 + j] = __float2half(tv);
        }
    }
    __syncthreads();                 // overlay dead; tile complete

    const unsigned my0 = smem_u32(&inbox[slot * 512 + t]);  // buffer0 slot word
    const unsigned my1 = my0 + 2048u * 4u;                  // buffer1
    unsigned pa0[4], pa1[4];
#pragma unroll
    for (int rk = 0; rk < 4; rk++) {
        pa0[rk] = mapa_rank(my0, rk);
        pa1[rk] = mapa_rank(my1, rk);
    }

    CLUSTER_SYNC();

    unsigned long long sv2[8], c2[8];
    float uhpr[8];                   // written only in last iteration

#define LOAD_SV() do {                                                       \
        const float4* ev4_ = (const float4*)ev;                              \
        float4 e0 = ev4_[lane * 2],      e1 = ev4_[lane * 2 + 1];            \
        float4 e2 = ev4_[64 + lane * 2], e3 = ev4_[64 + lane * 2 + 1];       \
        PACK2(sv2[0], e0.x, e0.y);  PACK2(sv2[1], e0.z, e0.w);               \
        PACK2(sv2[2], e1.x, e1.y);  PACK2(sv2[3], e1.z, e1.w);               \
        PACK2(sv2[4], e2.x, e2.y);  PACK2(sv2[5], e2.z, e2.w);               \
        PACK2(sv2[6], e3.x, e3.y);  PACK2(sv2[7], e3.z, e3.w);               \
    } while (0)

#define LOAD_X2(X2, ROW) do {                                                \
        const uint4* rp_ = (const uint4*)(tile + (ROW) * 512);               \
        uint4 q0 = rp_[lane], q1 = rp_[32 + lane];                           \
        float2 p_;                                                           \
        p_ = __half22float2(*(const __half2*)&q0.x); PACK2(X2[0], p_.x, p_.y);\
        p_ = __half22float2(*(const __half2*)&q0.y); PACK2(X2[1], p_.x, p_.y);\
        p_ = __half22float2(*(const __half2*)&q0.z); PACK2(X2[2], p_.x, p_.y);\
        p_ = __half22float2(*(const __half2*)&q0.w); PACK2(X2[3], p_.x, p_.y);\
        p_ = __half22float2(*(const __half2*)&q1.x); PACK2(X2[4], p_.x, p_.y);\
        p_ = __half22float2(*(const __half2*)&q1.y); PACK2(X2[5], p_.x, p_.y);\
        p_ = __half22float2(*(const __half2*)&q1.z); PACK2(X2[6], p_.x, p_.y);\
        p_ = __half22float2(*(const __half2*)&q1.w); PACK2(X2[7], p_.x, p_.y);\
    } while (0)

// row pass over 4 row-PAIRS: two interleaved dot/shfl/div chains per pair,
// packed dual-FP32 FMA for dot + column accumulation.
#define ROW_PASS(IS_FIRST, IS_LAST) do {                                     \
        _Pragma("unroll")                                                    \
        for (int p = 0; p < 8; p++) c2[p] = 0ull;                            \
        _Pragma("unroll")                                                    \
        for (int pp = 0; pp < 4; pp++) {                                     \
            const int ra = 2 * pp, rb = 2 * pp + 1;                          \
            unsigned long long xa2[8], xb2[8];                               \
            LOAD_X2(xa2, w * 8 + ra);                                        \
            LOAD_X2(xb2, w * 8 + rb);                                        \
            unsigned long long da2 = 0ull, db2 = 0ull;                       \
            _Pragma("unroll")                                                \
            for (int p = 0; p < 8; p++) {                                    \
                FMA2(da2, xa2[p], sv2[p], da2);                              \
                FMA2(db2, xb2[p], sv2[p], db2);                              \
            }                                                                \
            float a0_, a1_, b0_, b1_;                                        \
            UNPACK2(a0_, a1_, da2);  UNPACK2(b0_, b1_, db2);                 \
            float da = a0_ + a1_, db = b0_ + b1_;                            \
            _Pragma("unroll")                                                \
            for (int o = 16; o; o >>= 1) {                                   \
                da += __shfl_xor_sync(0xFFFFFFFFu, da, o);                   \
                db += __shfl_xor_sync(0xFFFFFFFFu, db, o);                   \
            }                                                                \
            float uhpa, uhpb;                                                \
            if (IS_FIRST) {                                                  \
                float dena = __fmaf_rn(da, scr[ra], mmask);                  \
                float denb = __fmaf_rn(db, scr[rb], mmask);                  \
                uhpa = __fdividef(ahr[ra] * scr[ra], fmaxf(dena, 1e-35f));   \
                uhpb = __fdividef(ahr[rb] * scr[rb], fmaxf(denb, 1e-35f));   \
            } else {                                                         \
                uhpa = __fdividef(ahr[ra], fmaxf(da, 1e-35f));               \
                uhpb = __fdividef(ahr[rb], fmaxf(db, 1e-35f));               \
            }                                                                \
            if (IS_LAST) { uhpr[ra] = uhpa; uhpr[rb] = uhpb; }               \
            unsigned long long uua, uub;                                     \
            PACK2(uua, uhpa, uhpa);  PACK2(uub, uhpb, uhpb);                 \
            _Pragma("unroll")                                                \
            for (int p = 0; p < 8; p++) {                                    \
                FMA2(c2[p], xa2[p], uua, c2[p]);                             \
                FMA2(c2[p], xb2[p], uub, c2[p]);                             \
            }                                                                \
        }                                                                    \
    } while (0)

// column-partial exchange into buffer BUFBIT of all 4 cluster CTAs.
#define EXCHANGE(BUFBIT) do {                                                \
        float4* cp = (float4*)(cpart + w * 512);                             \
        float f0_, f1_, f2_, f3_;                                            \
        UNPACK2(f0_, f1_, c2[0]); UNPACK2(f2_, f3_, c2[1]);                  \
        cp[lane * 2]      = make_float4(f0_, f1_, f2_, f3_);                 \
        UNPACK2(f0_, f1_, c2[2]); UNPACK2(f2_, f3_, c2[3]);                  \
        cp[lane * 2 + 1]  = make_float4(f0_, f1_, f2_, f3_);                 \
        UNPACK2(f0_, f1_, c2[4]); UNPACK2(f2_, f3_, c2[5]);                  \
        cp[64 + lane * 2] = make_float4(f0_, f1_, f2_, f3_);                 \
        UNPACK2(f0_, f1_, c2[6]); UNPACK2(f2_, f3_, c2[7]);                  \
        cp[65 + lane * 2] = make_float4(f0_, f1_, f2_, f3_);                 \
        __syncthreads();                                                     \
        float s_ = 0.f;                                                      \
        _Pragma("unroll")                                                    \
        for (int w2 = 0; w2 < 16; w2++) s_ += cpart[w2 * 512 + t];           \
        const unsigned* pa_ = (BUFBIT) ? pa1 : pa0;                          \
        _Pragma("unroll")                                                    \
        for (int rk = 0; rk < 4; rk++) st_cluster_f32(pa_[rk], s_);          \
        CLUSTER_SYNC();                                                      \
    } while (0)

#define COMPUTE_EV(RBUF) do {                                                \
        const float* ib_ = inbox + (RBUF) * 2048;                            \
        float S_ = ib_[t] + ib_[512 + t] + ib_[1024 + t] + ib_[1536 + t];    \
        ev[t] = bh / fmaxf(S_, 1e-35f);                                      \
        __syncthreads();                                                     \
    } while (0)

    // ---- iteration 0: ev = 1 everywhere (reference: logv starts at 0) ----
    ev[t] = 1.f;
    __syncthreads();
    LOAD_SV();
    ROW_PASS(1, 0);
    EXCHANGE(1);                       // it0 writes buffer1

    // ---- iterations 1..48 ----
    for (int it = 1; it < NITERS - 1; ++it) {
        COMPUTE_EV(it & 1);            // read buffer it&1
        LOAD_SV();
        ROW_PASS(0, 0);
        EXCHANGE((it + 1) & 1);        // write buffer (it+1)&1
    }

    // ---- iteration 49 (record final u-scalings) ----
    COMPUTE_EV(1);
    LOAD_SV();
    ROW_PASS(0, 1);
    EXCHANGE(0);

    // ---------------- fused epilogue: OT term + huber ----------------
    COMPUTE_EV(0);                     // final ev
    // scalar sv for epilogue
    float sve[16];
    {
        const float4* ev4_ = (const float4*)ev;
        float4 e0 = ev4_[lane * 2],      e1 = ev4_[lane * 2 + 1];
        float4 e2 = ev4_[64 + lane * 2], e3 = ev4_[64 + lane * 2 + 1];
        sve[0]=e0.x; sve[1]=e0.y; sve[2]=e0.z; sve[3]=e0.w;
        sve[4]=e1.x; sve[5]=e1.y; sve[6]=e1.z; sve[7]=e1.w;
        sve[8]=e2.x; sve[9]=e2.y; sve[10]=e2.z; sve[11]=e2.w;
        sve[12]=e3.x; sve[13]=e3.y; sve[14]=e3.z; sve[15]=e3.w;
    }

    float acc = 0.f;
#pragma unroll
    for (int r = 0; r < 8; r++) {
        float u = uhpr[r];
        if (u > 0.f) {
            const uint4* rp_ = (const uint4*)(tile + (w * 8 + r) * 512);
            uint4 q0 = rp_[lane], q1 = rp_[32 + lane];
            float x[16];
            float2 p_;
            p_ = __half22float2(*(const __half2*)&q0.x); x[0]=p_.x;  x[1]=p_.y;
            p_ = __half22float2(*(const __half2*)&q0.y); x[2]=p_.x;  x[3]=p_.y;
            p_ = __half22float2(*(const __half2*)&q0.z); x[4]=p_.x;  x[5]=p_.y;
            p_ = __half22float2(*(const __half2*)&q0.w); x[6]=p_.x;  x[7]=p_.y;
            p_ = __half22float2(*(const __half2*)&q1.x); x[8]=p_.x;  x[9]=p_.y;
            p_ = __half22float2(*(const __half2*)&q1.y); x[10]=p_.x; x[11]=p_.y;
            p_ = __half22float2(*(const __half2*)&q1.z); x[12]=p_.x; x[13]=p_.y;
            p_ = __half22float2(*(const __half2*)&q1.w); x[14]=p_.x; x[15]=p_.y;
            float mnr = row_mn[w * 8 + r];
#pragma unroll
            for (int k = 0; k < 16; k++) {
                if (x[k] > 0.f) {
                    float d = __fmaf_rn(SHIFT - __logf(x[k]), EPSV, mnr);
                    acc = __fmaf_rn(d * d, u * x[k] * sve[k], acc);
                }
            }
        }
    }
#pragma unroll
    for (int o = 16; o; o >>= 1) acc += __shfl_xor_sync(0xFFFFFFFFu, acc, o);
    if (lane == 0) cpart[w] = acc;     // cpart free after last EXCHANGE
    __syncthreads();
    if (t == 0) {
        float s = 0.f;
#pragma unroll
        for (int k = 0; k < 16; k++) s += cpart[k];
        st_cluster_f32(mapa_rank(smem_u32(&ot_in[slot]), 0), s);
    }
    CLUSTER_SYNC();
    if (slot == 0 && t == 0) {
        float e = sa - sb, ae = fabsf(e);
        float hub = (ae <= 1.f) ? 0.5f * e * e : (ae - 0.5f);
        out[batch] = hub + ot_in[0] + ot_in[1] + ot_in[2] + ot_in[3];
    }

#undef LOAD_SV
#undef LOAD_X2
#undef ROW_PASS
#undef EXCHANGE
#undef COMPUTE_EV
}

// ---------------------------------------------------------------------------
extern "C" void kernel_launch(void* const* d_in, const int* in_sizes, int n_in,
                              void* d_out, int out_size)
{
    const float* a_mask = (const float*)d_in[0];
    const float* pc_a   = (const float*)d_in[1];
    const float* b_mask = (const float*)d_in[2];
    const float* pc_b   = (const float*)d_in[3];
    float* out = (float*)d_out;

    // header (12936 floats, 16B-aligned end) + tile(fp16)
    static const int SMEM_BYTES =
        (512 + 16 * 512 + 8 * 512 + 128 + 8) * 4 + 128 * 512 * 2;  // 182,784 B
    cudaFuncSetAttribute(emd_fused_kernel,
                         cudaFuncAttributeMaxDynamicSharedMemorySize, SMEM_BYTES);

    emd_fused_kernel<<<4 * Bb, NTHR, SMEM_BYTES>>>(a_mask, pc_a, b_mask, pc_b, out);
}

// round 16
// speedup vs baseline: 1.0393x; 1.0393x over previous
#include <cuda_runtime.h>
#include <cuda_fp16.h>
#include <math.h>

#define Bb 32
#define EPSV 0.05f
#define INV_EPS 20.0f
#define SHIFT 10.0f
#define NITERS 50
#define NTHR 512            // 16 warps; warp owns 8 rows

// ---------------------------------------------------------------------------
__device__ __forceinline__ unsigned smem_u32(const void* p) {
    unsigned a;
    asm("{ .reg .u64 t; cvta.to.shared.u64 t, %1; cvt.u32.u64 %0, t; }"
        : "=r"(a) : "l"(p));
    return a;
}
__device__ __forceinline__ unsigned mapa_rank(unsigned addr, int rank) {
    unsigned r;
    asm("mapa.shared::cluster.u32 %0, %1, %2;" : "=r"(r) : "r"(addr), "r"(rank));
    return r;
}
__device__ __forceinline__ void st_cluster_f32(unsigned addr, float v) {
    asm volatile("st.shared::cluster.f32 [%0], %1;" :: "r"(addr), "f"(v));
}
#define CLUSTER_SYNC() do { \
    asm volatile("barrier.cluster.arrive.aligned;" ::: "memory"); \
    asm volatile("barrier.cluster.wait.aligned;"   ::: "memory"); \
} while (0)

// ---------------------------------------------------------------------------
// ONE kernel. grid = 128, block = 512, cluster(4) = 1 batch.
// smem: ev[512] | cpart[16*512] | inbox[2][4][512] | row_mn[128] | sc_s[128]
//       | u_s[128] | ot_in[4] | pad[4] | tile half[128*512]   (tile 16B-aligned)
__global__ void __launch_bounds__(NTHR, 1) __cluster_dims__(4, 1, 1)
emd_fused_kernel(const float* __restrict__ a_mask, const float* __restrict__ pc_a,
                 const float* __restrict__ b_mask, const float* __restrict__ pc_b,
                 float* __restrict__ out)
{
    extern __shared__ float smem[];
    float*  ev     = smem;                        // 512
    float*  cpart  = smem + 512;                  // 8192
    float*  inbox  = smem + 512 + 8192;           // 4096 (2 buf x 4 slot x 512)
    float*  row_mn = smem + 512 + 8192 + 4096;    // 128
    float*  sc_s   = row_mn + 128;                // 128 (it0 row scales)
    float*  u_s    = sc_s + 128;                  // 128 (final u-scalings)
    float*  ot_in  = u_s + 128;                   // 4 (+4 pad)
    __half* tile   = (__half*)(ot_in + 8);        // 16B-aligned (ofs 13192 f)

    const int batch = blockIdx.x >> 2, slot = blockIdx.x & 3;
    const int row_base = slot * 128;
    const int t = threadIdx.x, w = t >> 5, lane = t & 31;

    // ---------------- prep (each CTA computes full-batch stats) -------------
    int gb = batch * 512 + t;
    float apt = a_mask[gb] * pc_a[gb * 3 + 2];
    float bpt = b_mask[gb] * pc_b[gb * 3 + 2];
    inbox[t] = apt;                               // stash (buffer0, dead by it1)
    cpart[t] = apt; cpart[512 + t] = bpt; cpart[1024 + t] = (bpt > 0.f) ? 0.f : 1.f;
    __syncthreads();
    for (int o = 256; o; o >>= 1) {
        if (t < o) {
            cpart[t]        += cpart[t + o];
            cpart[512 + t]  += cpart[512 + t + o];
            cpart[1024 + t] += cpart[1024 + t + o];
        }
        __syncthreads();
    }
    const float sa = cpart[0], sb = cpart[512], mmask = cpart[1024];
    const float bh = bpt / sb;                    // masked -> 0
    __syncthreads();

    // overlay b columns into cpart
    cpart[t]        = pc_b[gb * 3 + 0];
    cpart[512 + t]  = pc_b[gb * 3 + 1];
    cpart[1024 + t] = bpt;
    __syncthreads();
    const float* bxs = cpart;
    const float* bys = cpart + 512;
    const float* bvs = cpart + 1024;

    // ---------------- build SMEM tile ----------------
    // t_ij = exp((dmin_i - d_ij)*INV_EPS + SHIFT), 0 for masked pairs.
    float ahr[8];
#pragma unroll
    for (int r = 0; r < 8; r++) {
        int row  = w * 8 + r;
        int grow = batch * 512 + row_base + row;
        float ax = pc_a[grow * 3 + 0], ay = pc_a[grow * 3 + 1];
        float ah = inbox[row_base + row] / sa;
        ahr[r] = ah;

        float dv[16], mn = 1e30f;
#pragma unroll
        for (int k = 0; k < 16; k++) {
            int j = k * 32 + lane;
            float dx = ax - bxs[j], dy = ay - bys[j];
            float d = sqrtf(__fmaf_rn(dx, dx, __fmaf_rn(dy, dy, 1e-12f)));
            dv[k] = d;
            if (bvs[j] > 0.f) mn = fminf(mn, d);
        }
#pragma unroll
        for (int o = 16; o; o >>= 1) mn = fminf(mn, __shfl_xor_sync(0xFFFFFFFFu, mn, o));
        if (lane == 0) {
            row_mn[row] = mn;
            sc_s[row]   = __expf(-__fmaf_rn(INV_EPS, mn, SHIFT)); // e^{-20mn-SHIFT}
        }

#pragma unroll
        for (int k = 0; k < 16; k++) {
            int j = k * 32 + lane;
            float arg = fminf((mn - dv[k]) * INV_EPS, 0.f) + SHIFT;
            float tv  = (bvs[j] > 0.f && ah > 0.f) ? __expf(arg) : 0.f;
            tile[row * 512 + j] = __float2half(tv);
        }
    }
    __syncthreads();                 // overlay dead; tile+sc_s complete

    const unsigned my0 = smem_u32(&inbox[slot * 512 + t]);  // buffer0 slot word
    const unsigned my1 = my0 + 2048u * 4u;                  // buffer1
    unsigned pa0[4], pa1[4];
#pragma unroll
    for (int rk = 0; rk < 4; rk++) {
        pa0[rk] = mapa_rank(my0, rk);
        pa1[rk] = mapa_rank(my1, rk);
    }

    CLUSTER_SYNC();

    float c[16], sv[16], xa[16], xb[16];

#define LOAD_SV() do {                                                       \
        const float4* ev4_ = (const float4*)ev;                              \
        float4 e0 = ev4_[lane * 2],      e1 = ev4_[lane * 2 + 1];            \
        float4 e2 = ev4_[64 + lane * 2], e3 = ev4_[64 + lane * 2 + 1];       \
        sv[0]=e0.x; sv[1]=e0.y; sv[2]=e0.z; sv[3]=e0.w;                      \
        sv[4]=e1.x; sv[5]=e1.y; sv[6]=e1.z; sv[7]=e1.w;                      \
        sv[8]=e2.x; sv[9]=e2.y; sv[10]=e2.z; sv[11]=e2.w;                    \
        sv[12]=e3.x; sv[13]=e3.y; sv[14]=e3.z; sv[15]=e3.w;                  \
    } while (0)

#define LOAD_X(X, ROW) do {                                                  \
        const uint4* rp_ = (const uint4*)(tile + (ROW) * 512);               \
        uint4 q0 = rp_[lane], q1 = rp_[32 + lane];                           \
        float2 p_;                                                           \
        p_ = __half22float2(*(const __half2*)&q0.x); X[0]=p_.x;  X[1]=p_.y;  \
        p_ = __half22float2(*(const __half2*)&q0.y); X[2]=p_.x;  X[3]=p_.y;  \
        p_ = __half22float2(*(const __half2*)&q0.z); X[4]=p_.x;  X[5]=p_.y;  \
        p_ = __half22float2(*(const __half2*)&q0.w); X[6]=p_.x;  X[7]=p_.y;  \
        p_ = __half22float2(*(const __half2*)&q1.x); X[8]=p_.x;  X[9]=p_.y;  \
        p_ = __half22float2(*(const __half2*)&q1.y); X[10]=p_.x; X[11]=p_.y; \
        p_ = __half22float2(*(const __half2*)&q1.z); X[12]=p_.x; X[13]=p_.y; \
        p_ = __half22float2(*(const __half2*)&q1.w); X[14]=p_.x; X[15]=p_.y; \
    } while (0)

// dot of X with sv (or plain pairwise sum if IS_FIRST) -- same order as R14
#define DOTP(DD, X, IS_FIRST) do {                                           \
        float d0, d1, d2, d3;                                                \
        if (IS_FIRST) {                                                      \
            d0 = (X[0]+X[1])+(X[2]+X[3]);   d1 = (X[4]+X[5])+(X[6]+X[7]);    \
            d2 = (X[8]+X[9])+(X[10]+X[11]); d3 = (X[12]+X[13])+(X[14]+X[15]);\
        } else {                                                             \
            d0 = d1 = d2 = d3 = 0.f;                                         \
            _Pragma("unroll")                                                \
            for (int q = 0; q < 4; q++) {                                    \
                d0 = __fmaf_rn(X[q],      sv[q],      d0);                   \
                d1 = __fmaf_rn(X[4 + q],  sv[4 + q],  d1);                   \
                d2 = __fmaf_rn(X[8 + q],  sv[8 + q],  d2);                   \
                d3 = __fmaf_rn(X[12 + q], sv[12 + q], d3);                   \
            }                                                                \
        }                                                                    \
        DD = (d0 + d1) + (d2 + d3);                                          \
    } while (0)

// reduce DD, compute u-scaling for local row R, accumulate columns from X
#define RED(X, DD, R, IS_FIRST, IS_LAST) do {                                \
        _Pragma("unroll")                                                    \
        for (int o = 16; o; o >>= 1)                                         \
            DD += __shfl_xor_sync(0xFFFFFFFFu, DD, o);                       \
        float uhp;                                                           \
        if (IS_FIRST) {                                                      \
            float sc_ = sc_s[w * 8 + (R)];                                   \
            float den = __fmaf_rn(DD, sc_, mmask);                           \
            uhp = __fdividef(ahr[R] * sc_, fmaxf(den, 1e-35f));              \
        } else {                                                             \
            uhp = __fdividef(ahr[R], fmaxf(DD, 1e-35f));                     \
        }                                                                    \
        if (IS_LAST && lane == 0) u_s[w * 8 + (R)] = uhp;                    \
        _Pragma("unroll")                                                    \
        for (int k = 0; k < 16; k++) c[k] = __fmaf_rn(X[k], uhp, c[k]);      \
    } while (0)

// software-pipelined row pass: load/dot of row r+2 issues between reductions
#define ROW_PASS(IS_FIRST, IS_LAST) do {                                     \
        float da, db;                                                        \
        _Pragma("unroll")                                                    \
        for (int k = 0; k < 16; k++) c[k] = 0.f;                             \
        LOAD_X(xa, w * 8 + 0); DOTP(da, xa, IS_FIRST);                       \
        LOAD_X(xb, w * 8 + 1); DOTP(db, xb, IS_FIRST);                       \
        RED(xa, da, 0, IS_FIRST, IS_LAST);                                   \
        LOAD_X(xa, w * 8 + 2); DOTP(da, xa, IS_FIRST);                       \
        RED(xb, db, 1, IS_FIRST, IS_LAST);                                   \
        LOAD_X(xb, w * 8 + 3); DOTP(db, xb, IS_FIRST);                       \
        RED(xa, da, 2, IS_FIRST, IS_LAST);                                   \
        LOAD_X(xa, w * 8 + 4); DOTP(da, xa, IS_FIRST);                       \
        RED(xb, db, 3, IS_FIRST, IS_LAST);                                   \
        LOAD_X(xb, w * 8 + 5); DOTP(db, xb, IS_FIRST);                       \
        RED(xa, da, 4, IS_FIRST, IS_LAST);                                   \
        LOAD_X(xa, w * 8 + 6); DOTP(da, xa, IS_FIRST);                       \
        RED(xb, db, 5, IS_FIRST, IS_LAST);                                   \
        LOAD_X(xb, w * 8 + 7); DOTP(db, xb, IS_FIRST);                       \
        RED(xa, da, 6, IS_FIRST, IS_LAST);                                   \
        RED(xb, db, 7, IS_FIRST, IS_LAST);                                   \
    } while (0)

// column-partial exchange into buffer BUFBIT of all 4 cluster CTAs.
#define EXCHANGE(BUFBIT) do {                                                \
        float4* cp = (float4*)(cpart + w * 512);                             \
        cp[lane * 2]      = make_float4(c[0],  c[1],  c[2],  c[3]);          \
        cp[lane * 2 + 1]  = make_float4(c[4],  c[5],  c[6],  c[7]);          \
        cp[64 + lane * 2] = make_float4(c[8],  c[9],  c[10], c[11]);         \
        cp[65 + lane * 2] = make_float4(c[12], c[13], c[14], c[15]);         \
        __syncthreads();                                                     \
        float s_ = 0.f;                                                      \
        _Pragma("unroll")                                                    \
        for (int w2 = 0; w2 < 16; w2++) s_ += cpart[w2 * 512 + t];           \
        const unsigned* pa_ = (BUFBIT) ? pa1 : pa0;                          \
        _Pragma("unroll")                                                    \
        for (int rk = 0; rk < 4; rk++) st_cluster_f32(pa_[rk], s_);          \
        CLUSTER_SYNC();                                                      \
    } while (0)

#define COMPUTE_EV(RBUF) do {                                                \
        const float* ib_ = inbox + (RBUF) * 2048;                            \
        float S_ = ib_[t] + ib_[512 + t] + ib_[1024 + t] + ib_[1536 + t];    \
        ev[t] = bh / fmaxf(S_, 1e-35f);                                      \
        __syncthreads();                                                     \
    } while (0)

    // ---- iteration 0 (ev = 1 everywhere; masked cols add Mmask*e^0) ----
    ROW_PASS(1, 0);
    EXCHANGE(1);                       // it0 writes buffer1

    // ---- iterations 1..48 ----
    for (int it = 1; it < NITERS - 1; ++it) {
        COMPUTE_EV(it & 1);            // read buffer it&1
        LOAD_SV();
        ROW_PASS(0, 0);
        EXCHANGE((it + 1) & 1);        // write buffer (it+1)&1
    }

    // ---- iteration 49 (record final u-scalings into u_s) ----
    COMPUTE_EV(1);
    LOAD_SV();
    ROW_PASS(0, 1);
    EXCHANGE(0);

    // ---------------- fused epilogue: OT term + huber ----------------
    COMPUTE_EV(0);                     // final ev
    LOAD_SV();

    float acc = 0.f;
#pragma unroll
    for (int r = 0; r < 8; r++) {
        float u = u_s[w * 8 + r];
        if (u > 0.f) {
            LOAD_X(xa, w * 8 + r);
            float mnr = row_mn[w * 8 + r];
#pragma unroll
            for (int k = 0; k < 16; k++) {
                if (xa[k] > 0.f) {
                    float d = __fmaf_rn(SHIFT - __logf(xa[k]), EPSV, mnr);
                    acc = __fmaf_rn(d * d, u * xa[k] * sv[k], acc);
                }
            }
        }
    }
#pragma unroll
    for (int o = 16; o; o >>= 1) acc += __shfl_xor_sync(0xFFFFFFFFu, acc, o);
    if (lane == 0) cpart[w] = acc;     // cpart free after last EXCHANGE
    __syncthreads();
    if (t == 0) {
        float s = 0.f;
#pragma unroll
        for (int k = 0; k < 16; k++) s += cpart[k];
        st_cluster_f32(mapa_rank(smem_u32(&ot_in[slot]), 0), s);
    }
    CLUSTER_SYNC();
    if (slot == 0 && t == 0) {
        float e = sa - sb, ae = fabsf(e);
        float hub = (ae <= 1.f) ? 0.5f * e * e : (ae - 0.5f);
        out[batch] = hub + ot_in[0] + ot_in[1] + ot_in[2] + ot_in[3];
    }

#undef LOAD_SV
#undef LOAD_X
#undef DOTP
#undef RED
#undef ROW_PASS
#undef EXCHANGE
#undef COMPUTE_EV
}

// ---------------------------------------------------------------------------
extern "C" void kernel_launch(void* const* d_in, const int* in_sizes, int n_in,
                              void* d_out, int out_size)
{
    const float* a_mask = (const float*)d_in[0];
    const float* pc_a   = (const float*)d_in[1];
    const float* b_mask = (const float*)d_in[2];
    const float* pc_b   = (const float*)d_in[3];
    float* out = (float*)d_out;

    // header (13192 floats, 16B-aligned end) + tile(fp16)
    static const int SMEM_BYTES =
        (512 + 16 * 512 + 8 * 512 + 128 + 128 + 128 + 8) * 4 + 128 * 512 * 2;
    cudaFuncSetAttribute(emd_fused_kernel,
                         cudaFuncAttributeMaxDynamicSharedMemorySize, SMEM_BYTES);

    emd_fused_kernel<<<4 * Bb, NTHR, SMEM_BYTES>>>(a_mask, pc_a, b_mask, pc_b, out);
}